// round 1
// baseline (speedup 1.0000x reference)
#include <cuda_runtime.h>
#include <math.h>

#define BQ    1024
#define NM    50000
#define DD    256
#define MAXA  200
#define KSEL  8
#define NSPLIT 37
#define SPLEN  1352            // ceil(50000/37); last split = 1328
#define NCAND (NSPLIT*KSEL)    // 296
#define BIGF  3.0e38f

// -------- device scratch (no allocations allowed) --------
__device__ float g_mem_hyp[NM * DD];   // 51.2 MB
__device__ float g_mem_sq[NM];
__device__ float g_q_hyp[BQ * DD];
__device__ float g_q_sq[BQ];
__device__ float g_cand_arg[BQ * NCAND];
__device__ int   g_cand_idx[BQ * NCAND];

// ============================================================
// Kernel 1: H = tanh(X@W + b), rescale into Poincare ball, plus row |h|^2.
// Tile: 64 rows x 256 cols, BK=16. 256 threads, 4x16 register blocking.
// row = ty + 16*i, col = tx + 16*j  (interleaved -> conflict-free smem reads)
// ============================================================
__global__ __launch_bounds__(256, 2)
void transform_kernel(const float* __restrict__ X, const float* __restrict__ W,
                      const float* __restrict__ bias,
                      float* __restrict__ H, float* __restrict__ SQ, int M)
{
    __shared__ float Xs[64][17];
    __shared__ float Ws[16][256];
    __shared__ float s_scale[64];

    const int tid = threadIdx.x;
    const int tx = tid & 15, ty = tid >> 4;
    const int row0 = blockIdx.x * 64;

    float acc[4][16];
#pragma unroll
    for (int i = 0; i < 4; i++)
#pragma unroll
        for (int j = 0; j < 16; j++) acc[i][j] = 0.f;

    for (int kc = 0; kc < DD; kc += 16) {
        // load X tile 64x16
#pragma unroll
        for (int e = tid; e < 64 * 16; e += 256) {
            int r = e >> 4, k = e & 15;
            float v = 0.f;
            if (row0 + r < M) v = X[(row0 + r) * DD + kc + k];
            Xs[r][k] = v;
        }
        // load W tile 16x256
#pragma unroll
        for (int e = tid; e < 16 * 256; e += 256) {
            int k = e >> 8, c = e & 255;
            Ws[k][c] = W[(kc + k) * DD + c];
        }
        __syncthreads();
#pragma unroll
        for (int k = 0; k < 16; k++) {
            float a[4], bb[16];
#pragma unroll
            for (int i = 0; i < 4; i++) a[i] = Xs[ty + 16 * i][k];
#pragma unroll
            for (int j = 0; j < 16; j++) bb[j] = Ws[k][tx + 16 * j];
#pragma unroll
            for (int i = 0; i < 4; i++)
#pragma unroll
                for (int j = 0; j < 16; j++)
                    acc[i][j] = fmaf(a[i], bb[j], acc[i][j]);
        }
        __syncthreads();
    }

    // bias + tanh + per-row sum of squares
    float psum[4];
#pragma unroll
    for (int i = 0; i < 4; i++) {
        psum[i] = 0.f;
#pragma unroll
        for (int j = 0; j < 16; j++) {
            float v = tanhf(acc[i][j] + bias[tx + 16 * j]);
            acc[i][j] = v;
            psum[i] += v * v;
        }
    }
    // reduce across the 16 tx lanes (xor<16 stays within half-warp)
#pragma unroll
    for (int off = 1; off < 16; off <<= 1) {
#pragma unroll
        for (int i = 0; i < 4; i++)
            psum[i] += __shfl_xor_sync(0xffffffffu, psum[i], off);
    }
    if (tx == 0) {
#pragma unroll
        for (int i = 0; i < 4; i++) {
            int r = ty + 16 * i;
            float norm = sqrtf(psum[i]);
            float sc = (norm > 0.95f) ? 0.95f / norm : 1.0f;
            s_scale[r] = sc;
            if (row0 + r < M) SQ[row0 + r] = psum[i] * sc * sc;
        }
    }
    __syncthreads();
#pragma unroll
    for (int i = 0; i < 4; i++) {
        int r = ty + 16 * i;
        if (row0 + r >= M) continue;
        float sc = s_scale[r];
#pragma unroll
        for (int j = 0; j < 16; j++)
            H[(row0 + r) * DD + tx + 16 * j] = acc[i][j] * sc;
    }
}

// ============================================================
// Kernel 2: fused dot-GEMM (128q x 128m x 256) + arg + running top-8
// grid = (BQ/128, NSPLIT). q = ty+16*i, m = tx+16*j.
// Owner thread (tid<128) maintains top-8 smallest args for its query.
// ============================================================
__global__ __launch_bounds__(256, 2)
void dist_topk_kernel()
{
    __shared__ float Qs[128][17];
    __shared__ float Ms[128][17];
    __shared__ float argbuf[128][33];   // 32 candidates per phase, +1 pad
    __shared__ float s_ta[128][KSEL];
    __shared__ int   s_ti[128][KSEL];

    const int tid = threadIdx.x;
    const int tx = tid & 15, ty = tid >> 4;
    const int q0 = blockIdx.x * 128;
    const int mstart = blockIdx.y * SPLEN;
    const int mend = min(mstart + SPLEN, NM);

    float xs[8], inv1x[8];
#pragma unroll
    for (int i = 0; i < 8; i++) {
        xs[i] = g_q_sq[q0 + ty + 16 * i];
        inv1x[i] = 1.0f - xs[i];
    }

    if (tid < 128) {
#pragma unroll
        for (int s = 0; s < KSEL; s++) { s_ta[tid][s] = BIGF; s_ti[tid][s] = 0x7fffffff; }
    }
    float worst = BIGF;
    __syncthreads();

    for (int m0 = mstart; m0 < mend; m0 += 128) {
        float acc[8][8];
#pragma unroll
        for (int i = 0; i < 8; i++)
#pragma unroll
            for (int j = 0; j < 8; j++) acc[i][j] = 0.f;

        for (int kc = 0; kc < DD; kc += 16) {
#pragma unroll
            for (int e = tid; e < 128 * 16; e += 256) {
                int r = e >> 4, k = e & 15;
                Qs[r][k] = g_q_hyp[(q0 + r) * DD + kc + k];
            }
#pragma unroll
            for (int e = tid; e < 128 * 16; e += 256) {
                int r = e >> 4, k = e & 15;
                int m = m0 + r;
                Ms[r][k] = (m < mend) ? g_mem_hyp[m * DD + kc + k] : 0.f;
            }
            __syncthreads();
#pragma unroll
            for (int k = 0; k < 16; k++) {
                float a[8], bb[8];
#pragma unroll
                for (int i = 0; i < 8; i++) a[i] = Qs[ty + 16 * i][k];
#pragma unroll
                for (int j = 0; j < 8; j++) bb[j] = Ms[tx + 16 * j][k];
#pragma unroll
                for (int i = 0; i < 8; i++)
#pragma unroll
                    for (int j = 0; j < 8; j++)
                        acc[i][j] = fmaf(a[i], bb[j], acc[i][j]);
            }
            __syncthreads();
        }

        float ys[8];
#pragma unroll
        for (int j = 0; j < 8; j++) {
            int m = m0 + tx + 16 * j;
            ys[j] = (m < mend) ? g_mem_sq[m] : 0.f;
        }

        // 4 phases of 32 candidates each: phase p covers j = 2p, 2p+1
#pragma unroll
        for (int p = 0; p < 4; p++) {
#pragma unroll
            for (int jj = 0; jj < 2; jj++) {
                int j = 2 * p + jj;
                int m = m0 + tx + 16 * j;
                bool valid = (m < mend);
#pragma unroll
                for (int i = 0; i < 8; i++) {
                    float d2 = fmaxf(xs[i] + ys[j] - 2.f * acc[i][j], 0.f);
                    float denom = inv1x[i] * (1.f - ys[j]) + 1e-8f;
                    float arg = 1.f + 2.f * d2 / denom;
                    argbuf[ty + 16 * i][tx + 16 * jj] = valid ? arg : BIGF;
                }
            }
            __syncthreads();
            if (tid < 128) {
                int q = tid;
                for (int c = 0; c < 32; c++) {
                    float a = argbuf[q][c];
                    if (a < worst) {
                        // replace current max slot
                        float mv = -1.f; int mp = 0;
#pragma unroll
                        for (int s = 0; s < KSEL; s++) {
                            float v = s_ta[q][s];
                            if (v > mv) { mv = v; mp = s; }
                        }
                        s_ta[q][mp] = a;
                        s_ti[q][mp] = m0 + 32 * p + c;
                        mv = -1.f;
#pragma unroll
                        for (int s = 0; s < KSEL; s++) {
                            float v = s_ta[q][s];
                            if (v > mv) mv = v;
                        }
                        worst = mv;
                    }
                }
            }
            __syncthreads();
        }
    }

    if (tid < 128) {
        int q = q0 + tid;
        int base = (q * NSPLIT + blockIdx.y) * KSEL;
#pragma unroll
        for (int s = 0; s < KSEL; s++) {
            g_cand_arg[base + s] = s_ta[tid][s];
            g_cand_idx[base + s] = s_ti[tid][s];
        }
    }
}

// ============================================================
// Kernel 3: merge 296 candidates/query -> final top-8 (rank by (dist,idx)
// to match jax.lax.top_k tie semantics), softmax weights, gather hints.
// out layout: [B*K weights][B*K*MAXA hints]
// ============================================================
__global__ void merge_kernel(const float* __restrict__ masks, float* __restrict__ out)
{
    __shared__ float cd[NCAND];
    __shared__ int   ci[NCAND];
    __shared__ float sel_d[KSEL];
    __shared__ int   sel_i[KSEL];

    const int q = blockIdx.x;
    const int tid = threadIdx.x;

    for (int c = tid; c < NCAND; c += 256) {
        float arg = fmaxf(g_cand_arg[q * NCAND + c], 1.0f + 1e-6f);
        cd[c] = acoshf(arg);
        ci[c] = g_cand_idx[q * NCAND + c];
    }
    __syncthreads();

    for (int c = tid; c < NCAND; c += 256) {
        float d = cd[c];
        int idx = ci[c];
        int rank = 0;
        for (int o = 0; o < NCAND; o++) {
            float od = cd[o];
            rank += (od < d) || (od == d && ci[o] < idx);
        }
        if (rank < KSEL) { sel_d[rank] = d; sel_i[rank] = idx; }
    }
    __syncthreads();

    if (tid == 0) {
        float d0 = sel_d[0];
        float e[KSEL], sum = 0.f;
#pragma unroll
        for (int s = 0; s < KSEL; s++) { e[s] = expf(d0 - sel_d[s]); sum += e[s]; }
        float inv = 1.0f / sum;
#pragma unroll
        for (int s = 0; s < KSEL; s++) out[q * KSEL + s] = e[s] * inv;
    }
    __syncthreads();

    float* hout = out + (size_t)BQ * KSEL;
    for (int e = tid; e < KSEL * MAXA; e += 256) {
        int s = e / MAXA, a = e - s * MAXA;
        hout[((size_t)q * KSEL + s) * MAXA + a] = masks[(size_t)sel_i[s] * MAXA + a];
    }
}

// ============================================================
extern "C" void kernel_launch(void* const* d_in, const int* in_sizes, int n_in,
                              void* d_out, int out_size)
{
    (void)in_sizes; (void)n_in; (void)out_size;
    const float* q_emb  = (const float*)d_in[0];
    const float* m_emb  = (const float*)d_in[1];
    const float* masks  = (const float*)d_in[2];
    const float* W      = (const float*)d_in[3];
    const float* bias   = (const float*)d_in[4];
    float* out = (float*)d_out;

    float *d_mh, *d_msq, *d_qh, *d_qsq;
    cudaGetSymbolAddress((void**)&d_mh,  g_mem_hyp);
    cudaGetSymbolAddress((void**)&d_msq, g_mem_sq);
    cudaGetSymbolAddress((void**)&d_qh,  g_q_hyp);
    cudaGetSymbolAddress((void**)&d_qsq, g_q_sq);

    transform_kernel<<<(NM + 63) / 64, 256>>>(m_emb, W, bias, d_mh, d_msq, NM);
    transform_kernel<<<(BQ + 63) / 64, 256>>>(q_emb, W, bias, d_qh, d_qsq, BQ);

    dim3 g2(BQ / 128, NSPLIT);
    dist_topk_kernel<<<g2, 256>>>();

    merge_kernel<<<BQ, 256>>>(masks, out);
}

// round 4
// speedup vs baseline: 1.2697x; 1.2697x over previous
#include <cuda_runtime.h>
#include <math.h>

#define BQ    1024
#define NM    50000
#define DD    256
#define MAXA  200
#define KSEL  8
#define NSPLIT 37
#define SPLEN  1352            // ceil(50000/37); last split = 1328
#define NCAND (NSPLIT*KSEL)    // 296
#define BIGF  3.0e38f

// -------- device scratch (no allocations allowed) --------
__device__ float g_mem_hyp[NM * DD];   // 51.2 MB
__device__ float g_mem_sq[NM];
__device__ float g_q_hyp[BQ * DD];
__device__ float g_q_sq[BQ];
__device__ float g_cand_arg[BQ * NCAND];
__device__ int   g_cand_idx[BQ * NCAND];

// -------- packed f32x2 helpers (FFMA2 — only reachable via PTX) --------
__device__ __forceinline__ unsigned long long dup2(float x) {
    unsigned long long r;
    asm("mov.b64 %0, {%1, %1};" : "=l"(r) : "f"(x));
    return r;
}
__device__ __forceinline__ void ffma2(unsigned long long& d,
                                      unsigned long long a, unsigned long long b) {
    asm("fma.rn.f32x2 %0, %1, %2, %0;" : "+l"(d) : "l"(a), "l"(b));
}
__device__ __forceinline__ float2 unpack2(unsigned long long v) {
    float2 r;
    asm("mov.b64 {%0, %1}, %2;" : "=f"(r.x), "=f"(r.y) : "l"(v));
    return r;
}

// ============================================================
// Kernel 1: H = tanh(X@W + b), rescale into Poincare ball, plus row |h|^2.
// 64 rows x 256 cols, BK=16, 256 threads. FFMA2: col pairs c = 2tx+32j(+1).
// ============================================================
__global__ __launch_bounds__(256, 2)
void transform_kernel(const float* __restrict__ X, const float* __restrict__ W,
                      const float* __restrict__ bias,
                      float* __restrict__ H, float* __restrict__ SQ, int M)
{
    __shared__ float  Xs[64][17];
    __shared__ float2 Ws2[16][128];     // k-major, col pairs
    __shared__ float  s_scale[64];

    const int tid = threadIdx.x;
    const int tx = tid & 15, ty = tid >> 4;
    const int row0 = blockIdx.x * 64;

    unsigned long long acc2[4][8];
#pragma unroll
    for (int i = 0; i < 4; i++)
#pragma unroll
        for (int j = 0; j < 8; j++) acc2[i][j] = 0ull;

    for (int kc = 0; kc < DD; kc += 16) {
#pragma unroll
        for (int e = tid; e < 64 * 16; e += 256) {
            int r = e >> 4, k = e & 15;
            float v = 0.f;
            if (row0 + r < M) v = X[(row0 + r) * DD + kc + k];
            Xs[r][k] = v;
        }
#pragma unroll
        for (int e = tid; e < 16 * 256; e += 256) {
            int k = e >> 8, c = e & 255;
            ((float*)Ws2)[k * 256 + c] = W[(kc + k) * DD + c];
        }
        __syncthreads();
#pragma unroll
        for (int k = 0; k < 16; k++) {
            unsigned long long a2[4], b2[8];
#pragma unroll
            for (int i = 0; i < 4; i++) a2[i] = dup2(Xs[ty + 16 * i][k]);
#pragma unroll
            for (int j = 0; j < 8; j++) {
                float2 bv = Ws2[k][tx + 16 * j];
                b2[j] = *(unsigned long long*)&bv;
            }
#pragma unroll
            for (int i = 0; i < 4; i++)
#pragma unroll
                for (int j = 0; j < 8; j++)
                    ffma2(acc2[i][j], a2[i], b2[j]);
        }
        __syncthreads();
    }

    const float2* bias2 = (const float2*)bias;
    float2 hv[4][8];
    float psum[4];
#pragma unroll
    for (int i = 0; i < 4; i++) {
        psum[i] = 0.f;
#pragma unroll
        for (int j = 0; j < 8; j++) {
            float2 bb = bias2[tx + 16 * j];
            float2 v = unpack2(acc2[i][j]);
            v.x = tanhf(v.x + bb.x);
            v.y = tanhf(v.y + bb.y);
            hv[i][j] = v;
            psum[i] += v.x * v.x + v.y * v.y;
        }
    }
#pragma unroll
    for (int off = 1; off < 16; off <<= 1) {
#pragma unroll
        for (int i = 0; i < 4; i++)
            psum[i] += __shfl_xor_sync(0xffffffffu, psum[i], off);
    }
    if (tx == 0) {
#pragma unroll
        for (int i = 0; i < 4; i++) {
            int r = ty + 16 * i;
            float norm = sqrtf(psum[i]);
            float sc = (norm > 0.95f) ? 0.95f / norm : 1.0f;
            s_scale[r] = sc;
            if (row0 + r < M) SQ[row0 + r] = psum[i] * sc * sc;
        }
    }
    __syncthreads();
    float2* H2 = (float2*)H;
#pragma unroll
    for (int i = 0; i < 4; i++) {
        int r = ty + 16 * i;
        if (row0 + r >= M) continue;
        float sc = s_scale[r];
#pragma unroll
        for (int j = 0; j < 8; j++) {
            float2 v = hv[i][j];
            v.x *= sc; v.y *= sc;
            H2[(size_t)(row0 + r) * 128 + tx + 16 * j] = v;
        }
    }
}

// ============================================================
// Kernel 2: fused dot-GEMM (128q x 128m x 256, FFMA2) + arg + running top-8
// grid = (BQ/128, NSPLIT). q = ty+16i; m pairs = 2tx+32j(+1).
// ============================================================
__global__ __launch_bounds__(256, 2)
void dist_topk_kernel()
{
    __shared__ float  Qsf[16][133];     // k-major q tile (pad 133: kills fill conflicts)
    __shared__ float2 Ms2[16][67];      // k-major m tile as pairs (134-float stride)
    __shared__ float  argbuf[128][33];
    __shared__ float  s_ta[128][KSEL];
    __shared__ int    s_ti[128][KSEL];

    const int tid = threadIdx.x;
    const int tx = tid & 15, ty = tid >> 4;
    const int q0 = blockIdx.x * 128;
    const int mstart = blockIdx.y * SPLEN;
    const int mend = min(mstart + SPLEN, NM);

    float xs[8], inv1x[8];
#pragma unroll
    for (int i = 0; i < 8; i++) {
        xs[i] = g_q_sq[q0 + ty + 16 * i];
        inv1x[i] = 1.0f - xs[i];
    }

    if (tid < 128) {
#pragma unroll
        for (int s = 0; s < KSEL; s++) { s_ta[tid][s] = BIGF; s_ti[tid][s] = 0x7fffffff; }
    }
    float worst = BIGF;
    __syncthreads();

    for (int m0 = mstart; m0 < mend; m0 += 128) {
        unsigned long long acc2[8][4];
#pragma unroll
        for (int i = 0; i < 8; i++)
#pragma unroll
            for (int j = 0; j < 4; j++) acc2[i][j] = 0ull;

        for (int kc = 0; kc < DD; kc += 16) {
            // fill Q tile (k-major): 512 float4 loads, scatter-transpose stores
#pragma unroll
            for (int it = 0; it < 2; it++) {
                int idx = tid + 256 * it;
                int q = idx >> 2, k4 = (idx & 3) * 4;
                float4 v = *(const float4*)&g_q_hyp[(size_t)(q0 + q) * DD + kc + k4];
                Qsf[k4 + 0][q] = v.x;
                Qsf[k4 + 1][q] = v.y;
                Qsf[k4 + 2][q] = v.z;
                Qsf[k4 + 3][q] = v.w;
            }
            // fill M tile (k-major)
            float* Msf = (float*)Ms2;
#pragma unroll
            for (int it = 0; it < 2; it++) {
                int idx = tid + 256 * it;
                int m = idx >> 2, k4 = (idx & 3) * 4;
                float4 v = make_float4(0.f, 0.f, 0.f, 0.f);
                if (m0 + m < mend)
                    v = *(const float4*)&g_mem_hyp[(size_t)(m0 + m) * DD + kc + k4];
                Msf[(k4 + 0) * 134 + m] = v.x;
                Msf[(k4 + 1) * 134 + m] = v.y;
                Msf[(k4 + 2) * 134 + m] = v.z;
                Msf[(k4 + 3) * 134 + m] = v.w;
            }
            __syncthreads();
#pragma unroll
            for (int k = 0; k < 16; k++) {
                unsigned long long a2[8], b2[4];
#pragma unroll
                for (int i = 0; i < 8; i++) a2[i] = dup2(Qsf[k][ty + 16 * i]);
#pragma unroll
                for (int j = 0; j < 4; j++) {
                    float2 bv = Ms2[k][tx + 16 * j];
                    b2[j] = *(unsigned long long*)&bv;
                }
#pragma unroll
                for (int i = 0; i < 8; i++)
#pragma unroll
                    for (int j = 0; j < 4; j++)
                        ffma2(acc2[i][j], a2[i], b2[j]);
            }
            __syncthreads();
        }

        // epilogue: 4 phases (one per m-pair j), 32 candidates each
#pragma unroll
        for (int p = 0; p < 4; p++) {
            int mA = m0 + 2 * tx + 32 * p;
            bool vA = (mA < mend), vB = (mA + 1 < mend);
            float ysA = vA ? g_mem_sq[mA] : 0.f;
            float ysB = vB ? g_mem_sq[mA + 1] : 0.f;
#pragma unroll
            for (int i = 0; i < 8; i++) {
                float2 av = unpack2(acc2[i][p]);
                float d2A = fmaxf(xs[i] + ysA - 2.f * av.x, 0.f);
                float d2B = fmaxf(xs[i] + ysB - 2.f * av.y, 0.f);
                float argA = 1.f + 2.f * d2A / (inv1x[i] * (1.f - ysA) + 1e-8f);
                float argB = 1.f + 2.f * d2B / (inv1x[i] * (1.f - ysB) + 1e-8f);
                argbuf[ty + 16 * i][2 * tx + 0] = vA ? argA : BIGF;
                argbuf[ty + 16 * i][2 * tx + 1] = vB ? argB : BIGF;
            }
            __syncthreads();
            if (tid < 128) {
                int q = tid;
                for (int c = 0; c < 32; c++) {
                    float a = argbuf[q][c];
                    if (a < worst) {
                        float mv = -1.f; int mp = 0;
#pragma unroll
                        for (int s = 0; s < KSEL; s++) {
                            float v = s_ta[q][s];
                            if (v > mv) { mv = v; mp = s; }
                        }
                        s_ta[q][mp] = a;
                        s_ti[q][mp] = m0 + 32 * p + c;
                        mv = -1.f;
#pragma unroll
                        for (int s = 0; s < KSEL; s++) {
                            float v = s_ta[q][s];
                            if (v > mv) mv = v;
                        }
                        worst = mv;
                    }
                }
            }
            __syncthreads();
        }
    }

    if (tid < 128) {
        int q = q0 + tid;
        int base = (q * NSPLIT + blockIdx.y) * KSEL;
#pragma unroll
        for (int s = 0; s < KSEL; s++) {
            g_cand_arg[base + s] = s_ta[tid][s];
            g_cand_idx[base + s] = s_ti[tid][s];
        }
    }
}

// ============================================================
// Kernel 3: merge 296 candidates/query -> top-8. Rank directly on the
// CLAMPED arg (arccosh is monotone, so ordering + tie semantics match the
// reference's clamped-dist ranking exactly); acosh only on the 8 finalists.
// ============================================================
__global__ void merge_kernel(const float* __restrict__ masks, float* __restrict__ out)
{
    __shared__ float ca[NCAND];
    __shared__ int   ci[NCAND];
    __shared__ float sel_a[KSEL];
    __shared__ int   sel_i[KSEL];

    const int q = blockIdx.x;
    const int tid = threadIdx.x;

    for (int c = tid; c < NCAND; c += 256) {
        ca[c] = fmaxf(g_cand_arg[q * NCAND + c], 1.0f + 1e-6f);
        ci[c] = g_cand_idx[q * NCAND + c];
    }
    __syncthreads();

    for (int c = tid; c < NCAND; c += 256) {
        float a = ca[c];
        int idx = ci[c];
        int rank = 0;
        for (int o = 0; o < NCAND; o++) {
            float oa = ca[o];
            rank += (oa < a) || (oa == a && ci[o] < idx);
        }
        if (rank < KSEL) { sel_a[rank] = a; sel_i[rank] = idx; }
    }
    __syncthreads();

    if (tid == 0) {
        float d[KSEL];
#pragma unroll
        for (int s = 0; s < KSEL; s++) d[s] = acoshf(sel_a[s]);
        float d0 = d[0];
        float e[KSEL], sum = 0.f;
#pragma unroll
        for (int s = 0; s < KSEL; s++) { e[s] = expf(d0 - d[s]); sum += e[s]; }
        float inv = 1.0f / sum;
#pragma unroll
        for (int s = 0; s < KSEL; s++) out[q * KSEL + s] = e[s] * inv;
    }
    __syncthreads();

    float* hout = out + (size_t)BQ * KSEL;
    for (int e = tid; e < KSEL * MAXA; e += 256) {
        int s = e / MAXA, a = e - s * MAXA;
        hout[((size_t)q * KSEL + s) * MAXA + a] = masks[(size_t)sel_i[s] * MAXA + a];
    }
}

// ============================================================
extern "C" void kernel_launch(void* const* d_in, const int* in_sizes, int n_in,
                              void* d_out, int out_size)
{
    (void)in_sizes; (void)n_in; (void)out_size;
    const float* q_emb  = (const float*)d_in[0];
    const float* m_emb  = (const float*)d_in[1];
    const float* masks  = (const float*)d_in[2];
    const float* W      = (const float*)d_in[3];
    const float* bias   = (const float*)d_in[4];
    float* out = (float*)d_out;

    float *d_mh, *d_msq, *d_qh, *d_qsq;
    cudaGetSymbolAddress((void**)&d_mh,  g_mem_hyp);
    cudaGetSymbolAddress((void**)&d_msq, g_mem_sq);
    cudaGetSymbolAddress((void**)&d_qh,  g_q_hyp);
    cudaGetSymbolAddress((void**)&d_qsq, g_q_sq);

    transform_kernel<<<(NM + 63) / 64, 256>>>(m_emb, W, bias, d_mh, d_msq, NM);
    transform_kernel<<<(BQ + 63) / 64, 256>>>(q_emb, W, bias, d_qh, d_qsq, BQ);

    dim3 g2(BQ / 128, NSPLIT);
    dist_topk_kernel<<<g2, 256>>>();

    merge_kernel<<<BQ, 256>>>(masks, out);
}